// round 14
// baseline (speedup 1.0000x reference)
#include <cuda_runtime.h>
#include <cuda_fp16.h>
#include <math.h>

#define N_NODES 50000
#define N_EDGES 800000
#define E_TOT   850000          // edges + self loops
#define IN_DIM  128
#define HID     64
#define HEADS   4
#define F1      256             // HEADS*HID
#define OUT_DIM 16
#define N_GRAPHS 500
#define NEG_SLOPE 0.2f
#define NCH 49                  // scan chunks of 1024

// ---------------- device scratch (static, no runtime alloc) ----------------
__device__ __align__(16) __half g_xh[N_NODES * IN_DIM];   // x in fp16
__device__ __align__(16) __half g_w1h[IN_DIM * F1];       // W1 fp16
__device__ __align__(16) __half g_w2h[HID * F1];          // W2 fp16
__device__ __align__(16) __half g_h[N_NODES * F1];        // post-GEMM features, fp16
__device__ __align__(16) __half g_hpost[N_NODES * HID];   // post-attention, fp16
__device__ __align__(16) float g_as[N_NODES * HEADS];
__device__ __align__(16) float g_ad[N_NODES * HEADS];
__device__ int g_count[N_NODES];       // zero-init; re-zeroed in k_scatter
__device__ int g_rowptr[N_NODES + 1];
__device__ int g_cursor[N_NODES];
__device__ int g_col[E_TOT];
__device__ int g_chunksum[64];
__device__ int g_bar_cnt;              // monotonic grid-barrier ticket counter

// ---------------- mma / cp.async helpers ----------------
__device__ __forceinline__ unsigned su32(const void* p) {
    return (unsigned)__cvta_generic_to_shared(p);
}
__device__ __forceinline__ void ldsm_x4(unsigned* r, unsigned addr) {
    asm volatile("ldmatrix.sync.aligned.m8n8.x4.shared.b16 {%0,%1,%2,%3}, [%4];"
        : "=r"(r[0]), "=r"(r[1]), "=r"(r[2]), "=r"(r[3]) : "r"(addr));
}
__device__ __forceinline__ void ldsm_x4_t(unsigned* r, unsigned addr) {
    asm volatile("ldmatrix.sync.aligned.m8n8.x4.trans.shared.b16 {%0,%1,%2,%3}, [%4];"
        : "=r"(r[0]), "=r"(r[1]), "=r"(r[2]), "=r"(r[3]) : "r"(addr));
}
__device__ __forceinline__ void mma16816(float* d, const unsigned* a, const unsigned* b) {
    asm volatile("mma.sync.aligned.m16n8k16.row.col.f32.f16.f16.f32 "
        "{%0,%1,%2,%3}, {%4,%5,%6,%7}, {%8,%9}, {%0,%1,%2,%3};"
        : "+f"(d[0]), "+f"(d[1]), "+f"(d[2]), "+f"(d[3])
        : "r"(a[0]), "r"(a[1]), "r"(a[2]), "r"(a[3]), "r"(b[0]), "r"(b[1]));
}
__device__ __forceinline__ void cp16(unsigned dst, const void* src) {
    asm volatile("cp.async.cg.shared.global [%0], [%1], 16;" :: "r"(dst), "l"(src));
}

// ============================================================================
// prep: x->fp16, W1/W2->fp16, dst histogram.  One kernel, independent tasks.
// ============================================================================
__global__ void k_prep(const float* __restrict__ x,
                       const float* __restrict__ W1,
                       const float* __restrict__ W2,
                       const int* __restrict__ ei)
{
    int i = blockIdx.x * blockDim.x + threadIdx.x;
    const int total4 = N_NODES * IN_DIM / 4;         // 1.6M
    if (i < total4) {
        float4 v = *(const float4*)(x + (long)i * 4);
        __half2* p = (__half2*)(g_xh + (long)i * 4);
        p[0] = __floats2half2_rn(v.x, v.y);
        p[1] = __floats2half2_rn(v.z, v.w);
    }
    const int n1 = IN_DIM * F1, n2 = HID * F1;
    if (i < n1) g_w1h[i] = __float2half_rn(W1[i]);
    else if (i < n1 + n2) g_w2h[i - n1] = __float2half_rn(W2[i - n1]);
    if (i < E_TOT) {
        int dst = (i < N_EDGES) ? ei[N_EDGES + i] : (i - N_EDGES);
        atomicAdd(&g_count[dst], 1);
    }
}

// ============================================================================
// CSR scan (49 blocks x 1024, one grid barrier via monotonic ticket counter)
// ============================================================================
__device__ __forceinline__ void grid_barrier() {
    __syncthreads();
    if (threadIdx.x == 0) {
        __threadfence();
        int t = atomicAdd(&g_bar_cnt, 1) + 1;
        int target = ((t + NCH - 1) / NCH) * NCH;
        while (atomicAdd(&g_bar_cnt, 0) < target) {}
        __threadfence();
    }
    __syncthreads();
}

__global__ __launch_bounds__(1024) void k_scan()
{
    __shared__ int sh[1024];
    __shared__ int s_off;
    int tid = threadIdx.x;
    int b = blockIdx.x;
    int i = b * 1024 + tid;

    int v = (i < N_NODES) ? g_count[i] : 0;
    sh[tid] = v;
    __syncthreads();
#pragma unroll
    for (int off = 1; off < 1024; off <<= 1) {
        int t = (tid >= off) ? sh[tid - off] : 0;
        __syncthreads();
        sh[tid] += t;
        __syncthreads();
    }
    if (tid == 1023) g_chunksum[b] = sh[1023];

    grid_barrier();

    if (tid == 0) {
        int run = 0;
        for (int c = 0; c < b; c++) run += g_chunksum[c];
        s_off = run;
    }
    __syncthreads();
    int off = s_off;

    if (i < N_NODES) {
        int val = sh[tid] + off;
        g_rowptr[i + 1] = val;
        if (i + 1 < N_NODES) g_cursor[i + 1] = val;
    }
    if (b == 0 && tid == 0) { g_rowptr[0] = 0; g_cursor[0] = 0; }
}

// scatter (full parallelism) + re-zero counts for next replay
__global__ void k_scatter(const int* __restrict__ ei) {
    int e = blockIdx.x * blockDim.x + threadIdx.x;
    if (e < N_NODES) g_count[e] = 0;
    if (e >= E_TOT) return;
    int src, dst;
    if (e < N_EDGES) { src = ei[e]; dst = ei[N_EDGES + e]; }
    else             { src = dst = e - N_EDGES; }
    int p = atomicAdd(&g_cursor[dst], 1);
    g_col[p] = src;
}

// ============================================================================
// HMMA GEMM: g_h[M,256](fp16) = A[M,K](fp16) @ W[K,256](fp16), fp32 acc.
// cp.async double-buffered, 3 blocks/SM (occupancy-focused). Fused as/ad.
// BM=64, BN=128 (grid.y=2), BK=32. 256 threads = 8 warps (4x2), warp=16x64.
// ============================================================================
#define SA 40
#define SB 136

template <int K, bool USE_X>
__global__ __launch_bounds__(256, 3) void k_gemm_hmma(
    const float* __restrict__ a_src, const float* __restrict__ a_dst)
{
    constexpr int NC = K / 32;
    __shared__ __half As[2][64][SA];     // 10.2 KB
    __shared__ __half Bs[2][32][SB];     // 17.4 KB

    const __half* A = USE_X ? g_xh : g_hpost;
    const __half* W = USE_X ? g_w1h : g_w2h;

    int tid = threadIdx.x;
    int lane = tid & 31, wid = tid >> 5;
    int wm = wid >> 1, wn = wid & 1;     // wm 0..3 (16 rows each), wn 0..1 (64 cols)
    int row0 = blockIdx.x * 64;
    int ncol0 = blockIdx.y * 128;

    int ar = tid >> 2, ac = tid & 3;     // A: 64 rows x 4 uint4 = 256 slots
    int bk = tid >> 4, bc = tid & 15;    // B: 2 iters of 16 rows x 16 uint4

    float acc[8][4];
#pragma unroll
    for (int ni = 0; ni < 8; ni++)
#pragma unroll
        for (int q = 0; q < 4; q++) acc[ni][q] = 0.f;

    auto load_chunk = [&](int kc, int b) {
        {
            int row = row0 + ar;
            row = row < N_NODES ? row : N_NODES - 1;   // clamp (never stored)
            cp16(su32(&As[b][ar][ac * 8]), A + (long)row * K + kc + ac * 8);
        }
#pragma unroll
        for (int it = 0; it < 2; it++) {
            int k = bk + it * 16;
            cp16(su32(&Bs[b][k][bc * 8]), W + (long)(kc + k) * 256 + ncol0 + bc * 8);
        }
        asm volatile("cp.async.commit_group;");
    };

    load_chunk(0, 0);

#pragma unroll
    for (int c = 0; c < NC; c++) {
        int b = c & 1;
        if (c + 1 < NC) {
            load_chunk((c + 1) * 32, (c + 1) & 1);
            asm volatile("cp.async.wait_group 1;");
        } else {
            asm volatile("cp.async.wait_group 0;");
        }
        __syncthreads();

#pragma unroll
        for (int ks = 0; ks < 32; ks += 16) {
            unsigned af[4];
            {
                unsigned ad = su32(&As[b][wm * 16 + (lane & 15)][ks + (lane >> 4) * 8]);
                ldsm_x4(af, ad);
            }
            unsigned bf[4][4];
#pragma unroll
            for (int j = 0; j < 4; j++) {
                unsigned bd = su32(&Bs[b][ks + (lane & 7) + ((lane >> 3) & 1) * 8]
                                        [wn * 64 + j * 16 + (lane >> 4) * 8]);
                ldsm_x4_t(bf[j], bd);
            }
#pragma unroll
            for (int j = 0; j < 4; j++) {
                mma16816(acc[2 * j],     af, &bf[j][0]);
                mma16816(acc[2 * j + 1], af, &bf[j][2]);
            }
        }
        __syncthreads();
    }

    // epilogue: fp16 h store + fused as/ad (fp32 accumulators)
    int head = blockIdx.y * 2 + wn;
    int col0 = ncol0 + wn * 64;
    float2 avv[8], dvv[8];
#pragma unroll
    for (int ni = 0; ni < 8; ni++) {
        int c = col0 + ni * 8 + (lane & 3) * 2;
        avv[ni] = *(const float2*)(a_src + c);
        dvv[ni] = *(const float2*)(a_dst + c);
    }
#pragma unroll
    for (int hf = 0; hf < 2; hf++) {
        int row = row0 + wm * 16 + hf * 8 + (lane >> 2);
        bool valid = row < N_NODES;
        float ps = 0.f, pd = 0.f;
#pragma unroll
        for (int ni = 0; ni < 8; ni++) {
            float d0 = acc[ni][hf * 2], d1 = acc[ni][hf * 2 + 1];
            ps += d0 * avv[ni].x + d1 * avv[ni].y;
            pd += d0 * dvv[ni].x + d1 * dvv[ni].y;
            if (valid) {
                __half2 q = __floats2half2_rn(d0, d1);
                *(__half2*)(g_h + (long)row * 256 + col0 + ni * 8 + (lane & 3) * 2) = q;
            }
        }
        ps += __shfl_xor_sync(0xFFFFFFFF, ps, 1);
        ps += __shfl_xor_sync(0xFFFFFFFF, ps, 2);
        pd += __shfl_xor_sync(0xFFFFFFFF, pd, 1);
        pd += __shfl_xor_sync(0xFFFFFFFF, pd, 2);
        if ((lane & 3) == 0 && valid) {
            g_as[row * HEADS + head] = ps;
            g_ad[row * HEADS + head] = pd;
        }
    }
}

// ============================================================================
// GAT attention — SINGLE PASS (unnormalized weights; normalize at the end).
// One warp per dst node.  At the L2-gather roofline (~38us/layer); unchanged.
// ============================================================================
__device__ __forceinline__ float lrelu(float v) {
    return v > 0.f ? v : NEG_SLOPE * v;
}

__global__ __launch_bounds__(256) void k_gat_attn(
    const float* __restrict__ bias)
{
    __shared__ __half s_ex[8][32][4];   // [warp][edge-in-chunk][head], ex*2^-8
    __shared__ int    s_src[8][32];

    int n = (blockIdx.x * blockDim.x + threadIdx.x) >> 5;
    int lane = threadIdx.x & 31;
    int wslot = (threadIdx.x >> 5);
    if (n >= N_NODES) return;

    int beg = g_rowptr[n], end = g_rowptr[n + 1];
    float4 adv = *(const float4*)(g_ad + n * 4);
    float ad0 = adv.x, ad1 = adv.y, ad2 = adv.z, ad3 = adv.w;

    const float SCALE = 1.f / 256.f;
    float se0 = 0.f, se1 = 0.f, se2 = 0.f, se3 = 0.f;
    int h0 = lane >> 3;
    int k0 = lane * 8;
    __half2 acc0 = __floats2half2_rn(0.f, 0.f);
    __half2 acc1 = acc0, acc2 = acc0, acc3 = acc0;

    for (int cs = beg; cs < end; cs += 32) {
        int nc = end - cs; if (nc > 32) nc = 32;
        if (lane < nc) {
            int s = g_col[cs + lane];
            float4 av = *(const float4*)(g_as + s * 4);
            float e0 = __expf(lrelu(av.x + ad0));
            float e1 = __expf(lrelu(av.y + ad1));
            float e2 = __expf(lrelu(av.z + ad2));
            float e3 = __expf(lrelu(av.w + ad3));
            se0 += e0; se1 += e1; se2 += e2; se3 += e3;
            __half2* ep = (__half2*)s_ex[wslot][lane];
            ep[0] = __floats2half2_rn(e0 * SCALE, e1 * SCALE);
            ep[1] = __floats2half2_rn(e2 * SCALE, e3 * SCALE);
            s_src[wslot][lane] = s;
        }
        __syncwarp();
        for (int j = 0; j < nc; j++) {
            int sj = s_src[wslot][j];
            __half2 aa = __half2half2(s_ex[wslot][j][h0]);
            uint4 raw = *(const uint4*)(g_h + (long)sj * F1 + k0);
            __half2* ph = (__half2*)&raw;
            acc0 = __hfma2(aa, ph[0], acc0);
            acc1 = __hfma2(aa, ph[1], acc1);
            acc2 = __hfma2(aa, ph[2], acc2);
            acc3 = __hfma2(aa, ph[3], acc3);
        }
        __syncwarp();
    }

#pragma unroll
    for (int off = 16; off >= 1; off >>= 1) {
        se0 += __shfl_xor_sync(0xFFFFFFFF, se0, off);
        se1 += __shfl_xor_sync(0xFFFFFFFF, se1, off);
        se2 += __shfl_xor_sync(0xFFFFFFFF, se2, off);
        se3 += __shfl_xor_sync(0xFFFFFFFF, se3, off);
    }
    float mysc = 256.f / ((h0 == 0) ? se0 : (h0 == 1) ? se1 : (h0 == 2) ? se2 : se3);

    float acc[8];
    { float2 f;
      f = __half22float2(acc0); acc[0] = f.x * mysc; acc[1] = f.y * mysc;
      f = __half22float2(acc1); acc[2] = f.x * mysc; acc[3] = f.y * mysc;
      f = __half22float2(acc2); acc[4] = f.x * mysc; acc[5] = f.y * mysc;
      f = __half22float2(acc3); acc[6] = f.x * mysc; acc[7] = f.y * mysc; }

#pragma unroll
    for (int k = 0; k < 8; k++) {
        acc[k] += __shfl_xor_sync(0xFFFFFFFF, acc[k], 8);
        acc[k] += __shfl_xor_sync(0xFFFFFFFF, acc[k], 16);
    }
    if (lane < 8) {
        __half* op = g_hpost + (long)n * HID + lane * 8;
        __half2 q[4];
#pragma unroll
        for (int k = 0; k < 4; k++) {
            float v0 = acc[2 * k]     * 0.25f + bias[lane * 8 + 2 * k];
            float v1 = acc[2 * k + 1] * 0.25f + bias[lane * 8 + 2 * k + 1];
            v0 = v0 > 0.f ? v0 : 0.f;
            v1 = v1 > 0.f ? v1 : 0.f;
            q[k] = __floats2half2_rn(v0, v1);
        }
        *(uint4*)op = *(uint4*)q;
    }
}

// ============================================================================
// pool (segment mean over sorted batch) + FC  (one block per graph, 64 thr)
// ============================================================================
__device__ __forceinline__ int lowerb(const int* b, int n, int v) {
    int lo = 0, hi = n;
    while (lo < hi) {
        int m = (lo + hi) >> 1;
        if (b[m] < v) lo = m + 1; else hi = m;
    }
    return lo;
}

__global__ __launch_bounds__(64) void k_pool_fc(
    const int* __restrict__ batch,
    const float* __restrict__ fcW, const float* __restrict__ fcb,
    float* __restrict__ out)
{
    int g = blockIdx.x;
    int d = threadIdx.x;
    int lo = lowerb(batch, N_NODES, g);
    int hi = lowerb(batch, N_NODES, g + 1);
    float acc = 0.f;
    for (int i = lo; i < hi; i++) acc += __half2float(g_hpost[(long)i * HID + d]);
    int cnt = hi - lo;
    float inv = 1.f / (float)(cnt > 0 ? cnt : 1);
    __shared__ float sp[HID];
    sp[d] = acc * inv;
    __syncthreads();
    if (d < OUT_DIM) {
        float o = fcb[d];
#pragma unroll
        for (int k = 0; k < HID; k++) o += sp[k] * fcW[k * OUT_DIM + d];
        out[g * OUT_DIM + d] = o;
    }
}

// ============================================================================
// launcher — 8 kernel launches, graph-capture safe
// ============================================================================
extern "C" void kernel_launch(void* const* d_in, const int* in_sizes, int n_in,
                              void* d_out, int out_size)
{
    const float* x     = (const float*)d_in[0];
    const int*   ei    = (const int*)d_in[1];     // int32 (JAX x64 disabled)
    const int*   batch = (const int*)d_in[2];     // int32
    const float* W1    = (const float*)d_in[3];
    const float* a1s   = (const float*)d_in[4];
    const float* a1d   = (const float*)d_in[5];
    const float* b1    = (const float*)d_in[6];
    const float* W2    = (const float*)d_in[7];
    const float* a2s   = (const float*)d_in[8];
    const float* a2d   = (const float*)d_in[9];
    const float* b2    = (const float*)d_in[10];
    const float* fcW   = (const float*)d_in[11];
    const float* fcb   = (const float*)d_in[12];
    float*       out   = (float*)d_out;

    dim3 ggrid((N_NODES + 63) / 64, 2);        // 782 x 2

    // 1: conversions + histogram
    k_prep<<<(N_NODES * IN_DIM / 4 + 255) / 256, 256>>>(x, W1, W2, ei);
    // 2: CSR scan
    k_scan<<<NCH, 1024>>>();
    // 3: scatter + count re-zero
    k_scatter<<<(E_TOT + 255) / 256, 256>>>(ei);
    // 4: layer-1 GEMM (+fused as/ad)   <- ncu capture slot
    k_gemm_hmma<IN_DIM, true><<<ggrid, 256>>>(a1s, a1d);
    // 5: layer-1 attention
    k_gat_attn<<<(N_NODES + 7) / 8, 256>>>(b1);
    // 6-7: layer 2
    k_gemm_hmma<HID, false><<<ggrid, 256>>>(a2s, a2d);
    k_gat_attn<<<(N_NODES + 7) / 8, 256>>>(b2);
    // 8: pool + fc
    k_pool_fc<<<N_GRAPHS, 64>>>(batch, fcW, fcb, out);
}

// round 15
// speedup vs baseline: 1.0212x; 1.0212x over previous
#include <cuda_runtime.h>
#include <cuda_fp16.h>
#include <math.h>

#define N_NODES 50000
#define N_EDGES 800000
#define E_TOT   850000          // edges + self loops
#define IN_DIM  128
#define HID     64
#define HEADS   4
#define F1      256             // HEADS*HID
#define OUT_DIM 16
#define N_GRAPHS 500
#define NEG_SLOPE 0.2f
#define NCH 49                  // scan chunks of 1024

// ---------------- device scratch (static, no runtime alloc) ----------------
__device__ __align__(16) __half g_xh[N_NODES * IN_DIM];   // x in fp16
__device__ __align__(16) __half g_w1h[IN_DIM * F1];       // W1 fp16
__device__ __align__(16) __half g_w2h[HID * F1];          // W2 fp16
__device__ __align__(16) __half g_h[N_NODES * F1];        // post-GEMM features, fp16
__device__ __align__(16) __half g_hpost[N_NODES * HID];   // post-attention, fp16
__device__ __align__(16) float g_as[N_NODES * HEADS];
__device__ __align__(16) float g_ad[N_NODES * HEADS];
__device__ int g_count[N_NODES];       // zero-init; re-zeroed in k_scatter
__device__ int g_rowptr[N_NODES + 1];
__device__ int g_cursor[N_NODES];
__device__ int g_col[E_TOT];
__device__ int g_chunksum[64];
__device__ int g_bar_cnt;              // monotonic grid-barrier ticket counter

// ---------------- mma / cp.async helpers ----------------
__device__ __forceinline__ unsigned su32(const void* p) {
    return (unsigned)__cvta_generic_to_shared(p);
}
__device__ __forceinline__ void ldsm_x4(unsigned* r, unsigned addr) {
    asm volatile("ldmatrix.sync.aligned.m8n8.x4.shared.b16 {%0,%1,%2,%3}, [%4];"
        : "=r"(r[0]), "=r"(r[1]), "=r"(r[2]), "=r"(r[3]) : "r"(addr));
}
__device__ __forceinline__ void ldsm_x4_t(unsigned* r, unsigned addr) {
    asm volatile("ldmatrix.sync.aligned.m8n8.x4.trans.shared.b16 {%0,%1,%2,%3}, [%4];"
        : "=r"(r[0]), "=r"(r[1]), "=r"(r[2]), "=r"(r[3]) : "r"(addr));
}
__device__ __forceinline__ void mma16816(float* d, const unsigned* a, const unsigned* b) {
    asm volatile("mma.sync.aligned.m16n8k16.row.col.f32.f16.f16.f32 "
        "{%0,%1,%2,%3}, {%4,%5,%6,%7}, {%8,%9}, {%0,%1,%2,%3};"
        : "+f"(d[0]), "+f"(d[1]), "+f"(d[2]), "+f"(d[3])
        : "r"(a[0]), "r"(a[1]), "r"(a[2]), "r"(a[3]), "r"(b[0]), "r"(b[1]));
}
__device__ __forceinline__ void cp16(unsigned dst, const void* src) {
    asm volatile("cp.async.cg.shared.global [%0], [%1], 16;" :: "r"(dst), "l"(src));
}

// ============================================================================
// prep: x->fp16, W1/W2->fp16, dst histogram.  One kernel, independent tasks.
// ============================================================================
__global__ void k_prep(const float* __restrict__ x,
                       const float* __restrict__ W1,
                       const float* __restrict__ W2,
                       const int* __restrict__ ei)
{
    int i = blockIdx.x * blockDim.x + threadIdx.x;
    const int total4 = N_NODES * IN_DIM / 4;         // 1.6M
    if (i < total4) {
        float4 v = *(const float4*)(x + (long)i * 4);
        __half2* p = (__half2*)(g_xh + (long)i * 4);
        p[0] = __floats2half2_rn(v.x, v.y);
        p[1] = __floats2half2_rn(v.z, v.w);
    }
    const int n1 = IN_DIM * F1, n2 = HID * F1;
    if (i < n1) g_w1h[i] = __float2half_rn(W1[i]);
    else if (i < n1 + n2) g_w2h[i - n1] = __float2half_rn(W2[i - n1]);
    if (i < E_TOT) {
        int dst = (i < N_EDGES) ? ei[N_EDGES + i] : (i - N_EDGES);
        atomicAdd(&g_count[dst], 1);
    }
}

// ============================================================================
// CSR scan (49 blocks x 1024, warp-shuffle based, one grid barrier)
// ============================================================================
__device__ __forceinline__ void grid_barrier() {
    __syncthreads();
    if (threadIdx.x == 0) {
        __threadfence();
        int t = atomicAdd(&g_bar_cnt, 1) + 1;
        int target = ((t + NCH - 1) / NCH) * NCH;
        while (atomicAdd(&g_bar_cnt, 0) < target) {}
        __threadfence();
    }
    __syncthreads();
}

__global__ __launch_bounds__(1024) void k_scan()
{
    __shared__ int s_wsum[32];
    __shared__ int s_off;
    int tid = threadIdx.x;
    int lane = tid & 31, wid = tid >> 5;
    int b = blockIdx.x;
    int i = b * 1024 + tid;

    int v = (i < N_NODES) ? g_count[i] : 0;

    // warp inclusive scan
    int sc = v;
#pragma unroll
    for (int off = 1; off < 32; off <<= 1) {
        int t = __shfl_up_sync(0xFFFFFFFF, sc, off);
        if (lane >= off) sc += t;
    }
    if (lane == 31) s_wsum[wid] = sc;
    __syncthreads();

    // warp 0 scans the 32 warp sums (inclusive)
    if (wid == 0) {
        int w = s_wsum[lane];
#pragma unroll
        for (int off = 1; off < 32; off <<= 1) {
            int t = __shfl_up_sync(0xFFFFFFFF, w, off);
            if (lane >= off) w += t;
        }
        s_wsum[lane] = w;
    }
    __syncthreads();

    int wofs = (wid > 0) ? s_wsum[wid - 1] : 0;
    int incl = sc + wofs;                      // block-local inclusive prefix
    if (tid == 1023) g_chunksum[b] = incl;

    grid_barrier();

    if (tid == 0) {
        int run = 0;
        for (int c = 0; c < b; c++) run += g_chunksum[c];
        s_off = run;
    }
    __syncthreads();
    int off = s_off;

    if (i < N_NODES) {
        int val = incl + off;
        g_rowptr[i + 1] = val;
        if (i + 1 < N_NODES) g_cursor[i + 1] = val;
    }
    if (b == 0 && tid == 0) { g_rowptr[0] = 0; g_cursor[0] = 0; }
}

// scatter (full parallelism) + re-zero counts for next replay
__global__ void k_scatter(const int* __restrict__ ei) {
    int e = blockIdx.x * blockDim.x + threadIdx.x;
    if (e < N_NODES) g_count[e] = 0;
    if (e >= E_TOT) return;
    int src, dst;
    if (e < N_EDGES) { src = ei[e]; dst = ei[N_EDGES + e]; }
    else             { src = dst = e - N_EDGES; }
    int p = atomicAdd(&g_cursor[dst], 1);
    g_col[p] = src;
}

// ============================================================================
// HMMA GEMM (R13 config — proven best): g_h[M,256](fp16) = A@W, fp32 acc.
// cp.async double-buffered, 2 blocks/SM. Fused as/ad epilogue.
// BM=128, BN=128 (grid.y=2), BK=32. 256 threads = 8 warps (4x2), warp=32x64.
// ============================================================================
#define SA 40
#define SB 136

template <int K, bool USE_X>
__global__ __launch_bounds__(256, 2) void k_gemm_hmma(
    const float* __restrict__ a_src, const float* __restrict__ a_dst)
{
    constexpr int NC = K / 32;
    __shared__ __half As[2][128][SA];
    __shared__ __half Bs[2][32][SB];

    const __half* A = USE_X ? g_xh : g_hpost;
    const __half* W = USE_X ? g_w1h : g_w2h;

    int tid = threadIdx.x;
    int lane = tid & 31, wid = tid >> 5;
    int wm = wid >> 1, wn = wid & 1;
    int row0 = blockIdx.x * 128;
    int ncol0 = blockIdx.y * 128;

    int ar = tid >> 2, ac = tid & 3;
    int bk = tid >> 4, bc = tid & 15;

    float acc[2][8][4];
#pragma unroll
    for (int mi = 0; mi < 2; mi++)
#pragma unroll
        for (int ni = 0; ni < 8; ni++)
#pragma unroll
            for (int q = 0; q < 4; q++) acc[mi][ni][q] = 0.f;

    auto load_chunk = [&](int kc, int b) {
#pragma unroll
        for (int it = 0; it < 2; it++) {
            int r = ar + it * 64;
            int row = row0 + r;
            row = row < N_NODES ? row : N_NODES - 1;   // clamp (never stored)
            cp16(su32(&As[b][r][ac * 8]), A + (long)row * K + kc + ac * 8);
        }
#pragma unroll
        for (int it = 0; it < 2; it++) {
            int k = bk + it * 16;
            cp16(su32(&Bs[b][k][bc * 8]), W + (long)(kc + k) * 256 + ncol0 + bc * 8);
        }
        asm volatile("cp.async.commit_group;");
    };

    load_chunk(0, 0);

#pragma unroll
    for (int c = 0; c < NC; c++) {
        int b = c & 1;
        if (c + 1 < NC) {
            load_chunk((c + 1) * 32, (c + 1) & 1);
            asm volatile("cp.async.wait_group 1;");
        } else {
            asm volatile("cp.async.wait_group 0;");
        }
        __syncthreads();

#pragma unroll
        for (int ks = 0; ks < 32; ks += 16) {
            unsigned af[2][4];
#pragma unroll
            for (int mi = 0; mi < 2; mi++) {
                unsigned ad = su32(&As[b][wm * 32 + mi * 16 + (lane & 15)][ks + (lane >> 4) * 8]);
                ldsm_x4(af[mi], ad);
            }
            unsigned bf[4][4];
#pragma unroll
            for (int j = 0; j < 4; j++) {
                unsigned bd = su32(&Bs[b][ks + (lane & 7) + ((lane >> 3) & 1) * 8]
                                        [wn * 64 + j * 16 + (lane >> 4) * 8]);
                ldsm_x4_t(bf[j], bd);
            }
#pragma unroll
            for (int mi = 0; mi < 2; mi++)
#pragma unroll
                for (int j = 0; j < 4; j++) {
                    mma16816(acc[mi][2 * j],     af[mi], &bf[j][0]);
                    mma16816(acc[mi][2 * j + 1], af[mi], &bf[j][2]);
                }
        }
        __syncthreads();
    }

    // epilogue: fp16 h store + fused as/ad (fp32 accumulators)
    int head = blockIdx.y * 2 + wn;
    int col0 = ncol0 + wn * 64;
    float2 avv[8], dvv[8];
#pragma unroll
    for (int ni = 0; ni < 8; ni++) {
        int c = col0 + ni * 8 + (lane & 3) * 2;
        avv[ni] = *(const float2*)(a_src + c);
        dvv[ni] = *(const float2*)(a_dst + c);
    }
#pragma unroll
    for (int mi = 0; mi < 2; mi++) {
#pragma unroll
        for (int hf = 0; hf < 2; hf++) {
            int row = row0 + wm * 32 + mi * 16 + hf * 8 + (lane >> 2);
            bool valid = row < N_NODES;
            float ps = 0.f, pd = 0.f;
#pragma unroll
            for (int ni = 0; ni < 8; ni++) {
                float d0 = acc[mi][ni][hf * 2], d1 = acc[mi][ni][hf * 2 + 1];
                ps += d0 * avv[ni].x + d1 * avv[ni].y;
                pd += d0 * dvv[ni].x + d1 * dvv[ni].y;
                if (valid) {
                    __half2 q = __floats2half2_rn(d0, d1);
                    *(__half2*)(g_h + (long)row * 256 + col0 + ni * 8 + (lane & 3) * 2) = q;
                }
            }
            ps += __shfl_xor_sync(0xFFFFFFFF, ps, 1);
            ps += __shfl_xor_sync(0xFFFFFFFF, ps, 2);
            pd += __shfl_xor_sync(0xFFFFFFFF, pd, 1);
            pd += __shfl_xor_sync(0xFFFFFFFF, pd, 2);
            if ((lane & 3) == 0 && valid) {
                g_as[row * HEADS + head] = ps;
                g_ad[row * HEADS + head] = pd;
            }
        }
    }
}

// ============================================================================
// GAT attention — SINGLE PASS (unnormalized weights; normalize at the end).
// One warp per dst node.  At the L2-gather roofline; unchanged from R13.
// ============================================================================
__device__ __forceinline__ float lrelu(float v) {
    return v > 0.f ? v : NEG_SLOPE * v;
}

__global__ __launch_bounds__(256) void k_gat_attn(
    const float* __restrict__ bias)
{
    __shared__ __half s_ex[8][32][4];   // [warp][edge-in-chunk][head], ex*2^-8
    __shared__ int    s_src[8][32];

    int n = (blockIdx.x * blockDim.x + threadIdx.x) >> 5;
    int lane = threadIdx.x & 31;
    int wslot = (threadIdx.x >> 5);
    if (n >= N_NODES) return;

    int beg = g_rowptr[n], end = g_rowptr[n + 1];
    float4 adv = *(const float4*)(g_ad + n * 4);
    float ad0 = adv.x, ad1 = adv.y, ad2 = adv.z, ad3 = adv.w;

    const float SCALE = 1.f / 256.f;
    float se0 = 0.f, se1 = 0.f, se2 = 0.f, se3 = 0.f;
    int h0 = lane >> 3;
    int k0 = lane * 8;
    __half2 acc0 = __floats2half2_rn(0.f, 0.f);
    __half2 acc1 = acc0, acc2 = acc0, acc3 = acc0;

    for (int cs = beg; cs < end; cs += 32) {
        int nc = end - cs; if (nc > 32) nc = 32;
        if (lane < nc) {
            int s = g_col[cs + lane];
            float4 av = *(const float4*)(g_as + s * 4);
            float e0 = __expf(lrelu(av.x + ad0));
            float e1 = __expf(lrelu(av.y + ad1));
            float e2 = __expf(lrelu(av.z + ad2));
            float e3 = __expf(lrelu(av.w + ad3));
            se0 += e0; se1 += e1; se2 += e2; se3 += e3;
            __half2* ep = (__half2*)s_ex[wslot][lane];
            ep[0] = __floats2half2_rn(e0 * SCALE, e1 * SCALE);
            ep[1] = __floats2half2_rn(e2 * SCALE, e3 * SCALE);
            s_src[wslot][lane] = s;
        }
        __syncwarp();
        for (int j = 0; j < nc; j++) {
            int sj = s_src[wslot][j];
            __half2 aa = __half2half2(s_ex[wslot][j][h0]);
            uint4 raw = *(const uint4*)(g_h + (long)sj * F1 + k0);
            __half2* ph = (__half2*)&raw;
            acc0 = __hfma2(aa, ph[0], acc0);
            acc1 = __hfma2(aa, ph[1], acc1);
            acc2 = __hfma2(aa, ph[2], acc2);
            acc3 = __hfma2(aa, ph[3], acc3);
        }
        __syncwarp();
    }

#pragma unroll
    for (int off = 16; off >= 1; off >>= 1) {
        se0 += __shfl_xor_sync(0xFFFFFFFF, se0, off);
        se1 += __shfl_xor_sync(0xFFFFFFFF, se1, off);
        se2 += __shfl_xor_sync(0xFFFFFFFF, se2, off);
        se3 += __shfl_xor_sync(0xFFFFFFFF, se3, off);
    }
    float mysc = 256.f / ((h0 == 0) ? se0 : (h0 == 1) ? se1 : (h0 == 2) ? se2 : se3);

    float acc[8];
    { float2 f;
      f = __half22float2(acc0); acc[0] = f.x * mysc; acc[1] = f.y * mysc;
      f = __half22float2(acc1); acc[2] = f.x * mysc; acc[3] = f.y * mysc;
      f = __half22float2(acc2); acc[4] = f.x * mysc; acc[5] = f.y * mysc;
      f = __half22float2(acc3); acc[6] = f.x * mysc; acc[7] = f.y * mysc; }

#pragma unroll
    for (int k = 0; k < 8; k++) {
        acc[k] += __shfl_xor_sync(0xFFFFFFFF, acc[k], 8);
        acc[k] += __shfl_xor_sync(0xFFFFFFFF, acc[k], 16);
    }
    if (lane < 8) {
        __half* op = g_hpost + (long)n * HID + lane * 8;
        __half2 q[4];
#pragma unroll
        for (int k = 0; k < 4; k++) {
            float v0 = acc[2 * k]     * 0.25f + bias[lane * 8 + 2 * k];
            float v1 = acc[2 * k + 1] * 0.25f + bias[lane * 8 + 2 * k + 1];
            v0 = v0 > 0.f ? v0 : 0.f;
            v1 = v1 > 0.f ? v1 : 0.f;
            q[k] = __floats2half2_rn(v0, v1);
        }
        *(uint4*)op = *(uint4*)q;
    }
}

// ============================================================================
// pool (segment mean over sorted batch) + FC  (one block per graph, 64 thr)
// ============================================================================
__device__ __forceinline__ int lowerb(const int* b, int n, int v) {
    int lo = 0, hi = n;
    while (lo < hi) {
        int m = (lo + hi) >> 1;
        if (b[m] < v) lo = m + 1; else hi = m;
    }
    return lo;
}

__global__ __launch_bounds__(64) void k_pool_fc(
    const int* __restrict__ batch,
    const float* __restrict__ fcW, const float* __restrict__ fcb,
    float* __restrict__ out)
{
    int g = blockIdx.x;
    int d = threadIdx.x;
    int lo = lowerb(batch, N_NODES, g);
    int hi = lowerb(batch, N_NODES, g + 1);
    float acc = 0.f;
    for (int i = lo; i < hi; i++) acc += __half2float(g_hpost[(long)i * HID + d]);
    int cnt = hi - lo;
    float inv = 1.f / (float)(cnt > 0 ? cnt : 1);
    __shared__ float sp[HID];
    sp[d] = acc * inv;
    __syncthreads();
    if (d < OUT_DIM) {
        float o = fcb[d];
#pragma unroll
        for (int k = 0; k < HID; k++) o += sp[k] * fcW[k * OUT_DIM + d];
        out[g * OUT_DIM + d] = o;
    }
}

// ============================================================================
// launcher — 8 kernel launches, graph-capture safe
// ============================================================================
extern "C" void kernel_launch(void* const* d_in, const int* in_sizes, int n_in,
                              void* d_out, int out_size)
{
    const float* x     = (const float*)d_in[0];
    const int*   ei    = (const int*)d_in[1];     // int32 (JAX x64 disabled)
    const int*   batch = (const int*)d_in[2];     // int32
    const float* W1    = (const float*)d_in[3];
    const float* a1s   = (const float*)d_in[4];
    const float* a1d   = (const float*)d_in[5];
    const float* b1    = (const float*)d_in[6];
    const float* W2    = (const float*)d_in[7];
    const float* a2s   = (const float*)d_in[8];
    const float* a2d   = (const float*)d_in[9];
    const float* b2    = (const float*)d_in[10];
    const float* fcW   = (const float*)d_in[11];
    const float* fcb   = (const float*)d_in[12];
    float*       out   = (float*)d_out;

    dim3 ggrid((N_NODES + 127) / 128, 2);      // 391 x 2

    // 1: conversions + histogram
    k_prep<<<(N_NODES * IN_DIM / 4 + 255) / 256, 256>>>(x, W1, W2, ei);
    // 2: CSR scan (warp-shuffle)
    k_scan<<<NCH, 1024>>>();
    // 3: scatter + count re-zero
    k_scatter<<<(E_TOT + 255) / 256, 256>>>(ei);
    // 4: layer-1 GEMM (+fused as/ad)   <- ncu capture slot
    k_gemm_hmma<IN_DIM, true><<<ggrid, 256>>>(a1s, a1d);
    // 5: layer-1 attention
    k_gat_attn<<<(N_NODES + 7) / 8, 256>>>(b1);
    // 6-7: layer 2
    k_gemm_hmma<HID, false><<<ggrid, 256>>>(a2s, a2d);
    k_gat_attn<<<(N_NODES + 7) / 8, 256>>>(b2);
    // 8: pool + fc
    k_pool_fc<<<N_GRAPHS, 64>>>(batch, fcW, fcb, out);
}